// round 11
// baseline (speedup 1.0000x reference)
#include <cuda_runtime.h>
#include <cuda_bf16.h>
#include <cuda_fp16.h>
#include <math.h>
#include <cstdint>

// CSELoss: loss = -mean_i [ s(i,i^1) - log(sum_{j!=i} exp(s_ij)) ], s = Xn Xn^T / alpha.
// Upper-triangle only; A-resident chunks, cp.async double-buffered B.
// Operands pre-scaled by sqrt(20*log2 e) -> acc is log2-domain; epilogue does
// packed f16x2 exp2 (half the MUFU/FADD/shfl of the scalar path).

#define NROWS 8192
#define DD    128
#define TILE  128
#define AINV  20.0f
#define SQSC  5.37158769f             // sqrt(20 * log2(e))
#define NT    (NROWS / TILE)          // 64
#define CHUNK 4
#define NCTAS 544                     // sum_{n=1..64} ceil(n/4)
#define STRB  272
#define ABYTES (128 * STRB)           // 34816

__device__ __nv_bfloat16  g_xb[NROWS * DD];
__device__ float          g_rowsum[NROWS];
__device__ float          g_tdot[NROWS / 2];

// ---------------------------------------------------------------------------
__device__ __forceinline__ uint32_t smem_u32(const void* p) {
    uint32_t a;
    asm("{ .reg .u64 t; cvta.to.shared.u64 t, %1; cvt.u32.u64 %0, t; }" : "=r"(a) : "l"(p));
    return a;
}
__device__ __forceinline__ void cp16(uint32_t dst, const void* src) {
    asm volatile("cp.async.cg.shared.global [%0], [%1], 16;" :: "r"(dst), "l"(src));
}
__device__ __forceinline__ void ldm_x4(uint32_t& r0, uint32_t& r1, uint32_t& r2,
                                       uint32_t& r3, uint32_t addr) {
    asm volatile("ldmatrix.sync.aligned.m8n8.x4.shared.b16 {%0,%1,%2,%3}, [%4];"
                 : "=r"(r0), "=r"(r1), "=r"(r2), "=r"(r3) : "r"(addr));
}
__device__ __forceinline__ void mma16816(float* c, const uint32_t* a,
                                         uint32_t b0, uint32_t b1) {
    asm volatile("mma.sync.aligned.m16n8k16.row.col.f32.bf16.bf16.f32 "
                 "{%0,%1,%2,%3}, {%4,%5,%6,%7}, {%8,%9}, {%0,%1,%2,%3};"
                 : "+f"(c[0]), "+f"(c[1]), "+f"(c[2]), "+f"(c[3])
                 : "r"(a[0]), "r"(a[1]), "r"(a[2]), "r"(a[3]), "r"(b0), "r"(b1));
}
__device__ __forceinline__ float ex2(float x) {
    float y;
    asm("ex2.approx.ftz.f32 %0, %1;" : "=f"(y) : "f"(x));
    return y;
}

// ---------------------------------------------------------------------------
__global__ void normalize_kernel(const float* __restrict__ in) {
    int gtid = blockIdx.x * blockDim.x + threadIdx.x;
    if (gtid < NROWS) g_rowsum[gtid] = 0.0f;
    int p    = gtid >> 5;
    int lane = threadIdx.x & 31;
    if (p >= NROWS / 2) return;
    int r0 = p * 2;
    float4 v0 = ((const float4*)(in + (size_t)r0 * DD))[lane];
    float4 v1 = ((const float4*)(in + (size_t)(r0 + 1) * DD))[lane];
    float ss0 = v0.x*v0.x + v0.y*v0.y + v0.z*v0.z + v0.w*v0.w;
    float ss1 = v1.x*v1.x + v1.y*v1.y + v1.z*v1.z + v1.w*v1.w;
    float d   = v0.x*v1.x + v0.y*v1.y + v0.z*v1.z + v0.w*v1.w;
#pragma unroll
    for (int o = 16; o; o >>= 1) {
        ss0 += __shfl_xor_sync(0xffffffffu, ss0, o);
        ss1 += __shfl_xor_sync(0xffffffffu, ss1, o);
        d   += __shfl_xor_sync(0xffffffffu, d,   o);
    }
    float i0 = 1.0f / fmaxf(sqrtf(ss0), 1e-8f);
    float i1 = 1.0f / fmaxf(sqrtf(ss1), 1e-8f);
    if (lane == 0) g_tdot[p] = d * i0 * i1;
    float s0 = i0 * SQSC, s1 = i1 * SQSC;
    v0.x *= s0; v0.y *= s0; v0.z *= s0; v0.w *= s0;
    v1.x *= s1; v1.y *= s1; v1.z *= s1; v1.w *= s1;
    __nv_bfloat162* b0 = (__nv_bfloat162*)(g_xb + (size_t)r0 * DD);
    __nv_bfloat162* b1 = (__nv_bfloat162*)(g_xb + (size_t)(r0 + 1) * DD);
    b0[lane*2+0] = __nv_bfloat162(__float2bfloat16_rn(v0.x), __float2bfloat16_rn(v0.y));
    b0[lane*2+1] = __nv_bfloat162(__float2bfloat16_rn(v0.z), __float2bfloat16_rn(v0.w));
    b1[lane*2+0] = __nv_bfloat162(__float2bfloat16_rn(v1.x), __float2bfloat16_rn(v1.y));
    b1[lane*2+1] = __nv_bfloat162(__float2bfloat16_rn(v1.z), __float2bfloat16_rn(v1.w));
}

// ---------------------------------------------------------------------------
__global__ __launch_bounds__(256, 2)
void expsum_mma_kernel() {
    extern __shared__ __align__(16) char sm[];
    uint32_t sA  = smem_u32(sm);
    uint32_t sB0 = sA + ABYTES;
    uint32_t sB1 = sB0 + ABYTES;
    __shared__ float rsum[TILE];
    __shared__ float csum[TILE];

    int tid  = threadIdx.x;
    int lane = tid & 31;
    int wid  = tid >> 5;
    int warp_m = wid & 3;
    int warp_n = wid >> 2;

    int t = blockIdx.x, bi = 0;
    int cpb = (NT + CHUNK - 1) / CHUNK;
    while (t >= cpb) { t -= cpb; bi++; cpb = (NT - bi + CHUNK - 1) / CHUNK; }
    int bjStart = bi + t * CHUNK;
    int ntile   = min(CHUNK, NT - bjStart);
    int rowBase = bi * TILE;

    int r8 = tid >> 4;
    int c8 = (tid & 15) << 3;
#pragma unroll
    for (int it = 0; it < 8; it++) {
        int r = r8 + it * 16;
        uint32_t so = (uint32_t)r * STRB + (uint32_t)c8 * 2;
        cp16(sA + so,  &g_xb[(size_t)(rowBase + r) * DD + c8]);
        cp16(sB0 + so, &g_xb[(size_t)(bjStart * TILE + r) * DD + c8]);
    }
    asm volatile("cp.async.commit_group;");
    if (tid < TILE) { rsum[tid] = 0.0f; csum[tid] = 0.0f; }
    asm volatile("cp.async.wait_group 0;" ::: "memory");
    __syncthreads();

    uint32_t lrow = lane & 15;
    uint32_t lcol = (lane >> 4) << 4;
    uint32_t aAddr  = sA + (warp_m * 32 + lrow) * STRB + lcol;
    uint32_t bLocal = (warp_n * 64 + lrow) * STRB + lcol;

    int q = lane >> 2, rm = lane & 3;
    float rs[2][2] = {{0.f, 0.f}, {0.f, 0.f}};
    const __half2 clamp2 = __floats2half2_rn(15.5f, 15.5f);

    for (int tt = 0; tt < ntile; tt++) {
        int bj = bjStart + tt;
        bool diag = (bj == bi);
        int colBase = bj * TILE;
        uint32_t bCur = (tt & 1) ? sB1 : sB0;
        uint32_t bNxt = (tt & 1) ? sB0 : sB1;

        if (tt + 1 < ntile) {
#pragma unroll
            for (int it = 0; it < 8; it++) {
                int r = r8 + it * 16;
                cp16(bNxt + (uint32_t)r * STRB + (uint32_t)c8 * 2,
                     &g_xb[(size_t)((bj + 1) * TILE + r) * DD + c8]);
            }
            asm volatile("cp.async.commit_group;");
        }

        float acc[2][8][4];
#pragma unroll
        for (int mf = 0; mf < 2; mf++)
#pragma unroll
            for (int nf = 0; nf < 8; nf++)
#pragma unroll
                for (int e = 0; e < 4; e++) acc[mf][nf][e] = 0.0f;

        uint32_t bAddr = bCur + bLocal;
#pragma unroll
        for (int kk = 0; kk < 8; kk++) {
            uint32_t ka = kk * 32;
            uint32_t a[2][4];
            ldm_x4(a[0][0], a[0][1], a[0][2], a[0][3], aAddr + ka);
            ldm_x4(a[1][0], a[1][1], a[1][2], a[1][3], aAddr + 16 * STRB + ka);
            uint32_t br[4][4];
#pragma unroll
            for (int nb = 0; nb < 4; nb++)
                ldm_x4(br[nb][0], br[nb][1], br[nb][2], br[nb][3],
                       bAddr + nb * 16 * STRB + ka);
#pragma unroll
            for (int mf = 0; mf < 2; mf++)
#pragma unroll
                for (int nf = 0; nf < 8; nf++) {
                    int nb = nf >> 1, odd = nf & 1;
                    mma16816(acc[mf][nf], a[mf], br[nb][odd], br[nb][odd + 2]);
                }
        }

        if (!diag) {
            // Packed f16x2 epilogue: lo half <-> col c, hi half <-> col c+1.
            __half2 csh[8];
#pragma unroll
            for (int nf = 0; nf < 8; nf++) csh[nf] = __floats2half2_rn(0.f, 0.f);
#pragma unroll
            for (int mf = 0; mf < 2; mf++) {
                __half2 rs0 = __floats2half2_rn(0.f, 0.f);
                __half2 rs1 = rs0;
#pragma unroll
                for (int nf = 0; nf < 8; nf++) {
                    __half2 t01 = __floats2half2_rn(acc[mf][nf][0], acc[mf][nf][1]);
                    __half2 t23 = __floats2half2_rn(acc[mf][nf][2], acc[mf][nf][3]);
                    __half2 p01 = h2exp2(__hmin2(t01, clamp2));
                    __half2 p23 = h2exp2(__hmin2(t23, clamp2));
                    rs0 = __hadd2(rs0, p01);
                    rs1 = __hadd2(rs1, p23);
                    csh[nf] = __hadd2(csh[nf], __hadd2(p01, p23));
                }
                rs[mf][0] += __low2float(rs0) + __high2float(rs0);
                rs[mf][1] += __low2float(rs1) + __high2float(rs1);
            }
            // Col-sum reduce over q lanes (half2), then smem atomics.
#pragma unroll
            for (int nf = 0; nf < 8; nf++) {
#pragma unroll
                for (int o = 4; o <= 16; o <<= 1)
                    csh[nf] = __hadd2(csh[nf],
                                      __shfl_xor_sync(0xffffffffu, csh[nf], o));
            }
            if (q == 0) {
#pragma unroll
                for (int nf = 0; nf < 8; nf++) {
                    int c = warp_n * 64 + nf * 8 + rm * 2;
                    atomicAdd(&csum[c],     __low2float(csh[nf]));
                    atomicAdd(&csum[c + 1], __high2float(csh[nf]));
                }
            }
            __syncthreads();
            if (tid < TILE) {
                atomicAdd(&g_rowsum[colBase + tid], csum[tid]);
                csum[tid] = 0.0f;
            }
        } else {
            // Diagonal tile: exact scalar path with masking.
#pragma unroll
            for (int mf = 0; mf < 2; mf++) {
                int gr0 = rowBase + warp_m * 32 + mf * 16 + q;
                int gr1 = gr0 + 8;
#pragma unroll
                for (int nf = 0; nf < 8; nf++) {
                    int gc = colBase + warp_n * 64 + nf * 8 + rm * 2;
                    float e0 = ex2(acc[mf][nf][0]);
                    float e1 = ex2(acc[mf][nf][1]);
                    float e2 = ex2(acc[mf][nf][2]);
                    float e3 = ex2(acc[mf][nf][3]);
                    if (gr0 == gc)     e0 = 0.0f;
                    if (gr0 == gc + 1) e1 = 0.0f;
                    if (gr1 == gc)     e2 = 0.0f;
                    if (gr1 == gc + 1) e3 = 0.0f;
                    rs[mf][0] += e0 + e1;
                    rs[mf][1] += e2 + e3;
                }
            }
        }

        asm volatile("cp.async.wait_group 0;" ::: "memory");
        __syncthreads();
    }

#pragma unroll
    for (int mf = 0; mf < 2; mf++) {
        float s0 = rs[mf][0], s1 = rs[mf][1];
        s0 += __shfl_xor_sync(0xffffffffu, s0, 1);
        s0 += __shfl_xor_sync(0xffffffffu, s0, 2);
        s1 += __shfl_xor_sync(0xffffffffu, s1, 1);
        s1 += __shfl_xor_sync(0xffffffffu, s1, 2);
        if (rm == 0) {
            int r0 = warp_m * 32 + mf * 16 + q;
            atomicAdd(&rsum[r0], s0);
            atomicAdd(&rsum[r0 + 8], s1);
        }
    }
    __syncthreads();
    if (tid < TILE) atomicAdd(&g_rowsum[rowBase + tid], rsum[tid]);
}

// ---------------------------------------------------------------------------
__global__ void finalize_kernel(float* out) {
    __shared__ float red[32];
    int tid = threadIdx.x;
    float l = 0.0f;
    for (int i = tid; i < NROWS; i += 1024)
        l += AINV * g_tdot[i >> 1] - logf(g_rowsum[i]);
#pragma unroll
    for (int o = 16; o; o >>= 1) l += __shfl_xor_sync(0xffffffffu, l, o);
    if ((tid & 31) == 0) red[tid >> 5] = l;
    __syncthreads();
    if (tid < 32) {
        float v = red[tid];
#pragma unroll
        for (int o = 16; o; o >>= 1) v += __shfl_xor_sync(0xffffffffu, v, o);
        if (tid == 0) out[0] = -v * (1.0f / NROWS);
    }
}

// ---------------------------------------------------------------------------
extern "C" void kernel_launch(void* const* d_in, const int* in_sizes, int n_in,
                              void* d_out, int out_size) {
    const float* in = (const float*)d_in[0];
    float* out = (float*)d_out;
    (void)in_sizes; (void)n_in; (void)out_size;

    int dynBytes = 3 * ABYTES;   // 104448
    (void)cudaFuncSetAttribute(expsum_mma_kernel,
                               cudaFuncAttributeMaxDynamicSharedMemorySize,
                               dynBytes);

    normalize_kernel<<<NROWS / 2 / 8, 256>>>(in);
    expsum_mma_kernel<<<NCTAS, 256, dynBytes>>>();
    finalize_kernel<<<1, 1024>>>(out);
}

// round 13
// speedup vs baseline: 1.1405x; 1.1405x over previous
#include <cuda_runtime.h>
#include <cuda_bf16.h>
#include <math.h>
#include <cstdint>

// CSELoss: loss = -mean_i [ s(i,i^1) - log(sum_{j!=i} exp(s_ij)) ], s = Xn Xn^T / alpha.
// Upper-triangle only; A-resident chunks (CHUNK=8 -> single wave), cp.async
// double-buffered B, one barrier per tile, col-sums via direct gmem REDG.
// Operands pre-scaled by sqrt(20*log2 e) -> epilogue is a single ex2 per element.

#define NROWS 8192
#define DD    128
#define TILE  128
#define AINV  20.0f
#define SQSC  5.37158769f             // sqrt(20 * log2(e))
#define NT    (NROWS / TILE)          // 64
#define CHUNK 8
#define NCTAS 288                     // sum_{n=1..64} ceil(n/8)
#define STRB  272
#define ABYTES (128 * STRB)           // 34816

__device__ __nv_bfloat16  g_xb[NROWS * DD];
__device__ float          g_rowsum[NROWS];
__device__ float          g_tdot[NROWS / 2];

// ---------------------------------------------------------------------------
__device__ __forceinline__ uint32_t smem_u32(const void* p) {
    uint32_t a;
    asm("{ .reg .u64 t; cvta.to.shared.u64 t, %1; cvt.u32.u64 %0, t; }" : "=r"(a) : "l"(p));
    return a;
}
__device__ __forceinline__ void cp16(uint32_t dst, const void* src) {
    asm volatile("cp.async.cg.shared.global [%0], [%1], 16;" :: "r"(dst), "l"(src));
}
__device__ __forceinline__ void ldm_x4(uint32_t& r0, uint32_t& r1, uint32_t& r2,
                                       uint32_t& r3, uint32_t addr) {
    asm volatile("ldmatrix.sync.aligned.m8n8.x4.shared.b16 {%0,%1,%2,%3}, [%4];"
                 : "=r"(r0), "=r"(r1), "=r"(r2), "=r"(r3) : "r"(addr));
}
__device__ __forceinline__ void mma16816(float* c, const uint32_t* a,
                                         uint32_t b0, uint32_t b1) {
    asm volatile("mma.sync.aligned.m16n8k16.row.col.f32.bf16.bf16.f32 "
                 "{%0,%1,%2,%3}, {%4,%5,%6,%7}, {%8,%9}, {%0,%1,%2,%3};"
                 : "+f"(c[0]), "+f"(c[1]), "+f"(c[2]), "+f"(c[3])
                 : "r"(a[0]), "r"(a[1]), "r"(a[2]), "r"(a[3]), "r"(b0), "r"(b1));
}
__device__ __forceinline__ float ex2(float x) {
    float y;
    asm("ex2.approx.ftz.f32 %0, %1;" : "=f"(y) : "f"(x));
    return y;
}

// ---------------------------------------------------------------------------
__global__ void normalize_kernel(const float* __restrict__ in) {
    int gtid = blockIdx.x * blockDim.x + threadIdx.x;
    if (gtid < NROWS) g_rowsum[gtid] = 0.0f;
    int p    = gtid >> 5;
    int lane = threadIdx.x & 31;
    if (p >= NROWS / 2) return;
    int r0 = p * 2;
    float4 v0 = ((const float4*)(in + (size_t)r0 * DD))[lane];
    float4 v1 = ((const float4*)(in + (size_t)(r0 + 1) * DD))[lane];
    float ss0 = v0.x*v0.x + v0.y*v0.y + v0.z*v0.z + v0.w*v0.w;
    float ss1 = v1.x*v1.x + v1.y*v1.y + v1.z*v1.z + v1.w*v1.w;
    float d   = v0.x*v1.x + v0.y*v1.y + v0.z*v1.z + v0.w*v1.w;
#pragma unroll
    for (int o = 16; o; o >>= 1) {
        ss0 += __shfl_xor_sync(0xffffffffu, ss0, o);
        ss1 += __shfl_xor_sync(0xffffffffu, ss1, o);
        d   += __shfl_xor_sync(0xffffffffu, d,   o);
    }
    float i0 = 1.0f / fmaxf(sqrtf(ss0), 1e-8f);
    float i1 = 1.0f / fmaxf(sqrtf(ss1), 1e-8f);
    if (lane == 0) g_tdot[p] = d * i0 * i1;
    float s0 = i0 * SQSC, s1 = i1 * SQSC;
    v0.x *= s0; v0.y *= s0; v0.z *= s0; v0.w *= s0;
    v1.x *= s1; v1.y *= s1; v1.z *= s1; v1.w *= s1;
    __nv_bfloat162* b0 = (__nv_bfloat162*)(g_xb + (size_t)r0 * DD);
    __nv_bfloat162* b1 = (__nv_bfloat162*)(g_xb + (size_t)(r0 + 1) * DD);
    b0[lane*2+0] = __nv_bfloat162(__float2bfloat16_rn(v0.x), __float2bfloat16_rn(v0.y));
    b0[lane*2+1] = __nv_bfloat162(__float2bfloat16_rn(v0.z), __float2bfloat16_rn(v0.w));
    b1[lane*2+0] = __nv_bfloat162(__float2bfloat16_rn(v1.x), __float2bfloat16_rn(v1.y));
    b1[lane*2+1] = __nv_bfloat162(__float2bfloat16_rn(v1.z), __float2bfloat16_rn(v1.w));
}

// ---------------------------------------------------------------------------
__global__ __launch_bounds__(256, 2)
void expsum_mma_kernel() {
    extern __shared__ __align__(16) char sm[];
    uint32_t sA  = smem_u32(sm);
    uint32_t sB0 = sA + ABYTES;
    uint32_t sB1 = sB0 + ABYTES;
    __shared__ float rsum[TILE];

    int tid  = threadIdx.x;
    int lane = tid & 31;
    int wid  = tid >> 5;
    int warp_m = wid & 3;
    int warp_n = wid >> 2;

    // blockIdx -> (band bi, chunk start bjStart, ntile)
    int t = blockIdx.x, bi = 0;
    int cpb = (NT + CHUNK - 1) / CHUNK;
    while (t >= cpb) { t -= cpb; bi++; cpb = (NT - bi + CHUNK - 1) / CHUNK; }
    int bjStart = bi + t * CHUNK;
    int ntile   = min(CHUNK, NT - bjStart);
    int rowBase = bi * TILE;

    int r8 = tid >> 4;
    int c8 = (tid & 15) << 3;
#pragma unroll
    for (int it = 0; it < 8; it++) {
        int r = r8 + it * 16;
        uint32_t so = (uint32_t)r * STRB + (uint32_t)c8 * 2;
        cp16(sA + so,  &g_xb[(size_t)(rowBase + r) * DD + c8]);
        cp16(sB0 + so, &g_xb[(size_t)(bjStart * TILE + r) * DD + c8]);
    }
    asm volatile("cp.async.commit_group;");
    if (tid < TILE) rsum[tid] = 0.0f;
    asm volatile("cp.async.wait_group 0;" ::: "memory");
    __syncthreads();

    uint32_t lrow = lane & 15;
    uint32_t lcol = (lane >> 4) << 4;
    uint32_t aAddr  = sA + (warp_m * 32 + lrow) * STRB + lcol;
    uint32_t bLocal = (warp_n * 64 + lrow) * STRB + lcol;

    int q = lane >> 2, rm = lane & 3;
    float rs[2][2] = {{0.f, 0.f}, {0.f, 0.f}};

    for (int tt = 0; tt < ntile; tt++) {
        int bj = bjStart + tt;
        bool diag = (bj == bi);
        int colBase = bj * TILE;
        uint32_t bCur = (tt & 1) ? sB1 : sB0;
        uint32_t bNxt = (tt & 1) ? sB0 : sB1;

        if (tt + 1 < ntile) {
#pragma unroll
            for (int it = 0; it < 8; it++) {
                int r = r8 + it * 16;
                cp16(bNxt + (uint32_t)r * STRB + (uint32_t)c8 * 2,
                     &g_xb[(size_t)((bj + 1) * TILE + r) * DD + c8]);
            }
            asm volatile("cp.async.commit_group;");
        }

        float acc[2][8][4];
#pragma unroll
        for (int mf = 0; mf < 2; mf++)
#pragma unroll
            for (int nf = 0; nf < 8; nf++)
#pragma unroll
                for (int e = 0; e < 4; e++) acc[mf][nf][e] = 0.0f;

        uint32_t bAddr = bCur + bLocal;
#pragma unroll
        for (int kk = 0; kk < 8; kk++) {
            uint32_t ka = kk * 32;
            uint32_t a[2][4];
            ldm_x4(a[0][0], a[0][1], a[0][2], a[0][3], aAddr + ka);
            ldm_x4(a[1][0], a[1][1], a[1][2], a[1][3], aAddr + 16 * STRB + ka);
            uint32_t br[4][4];
#pragma unroll
            for (int nb = 0; nb < 4; nb++)
                ldm_x4(br[nb][0], br[nb][1], br[nb][2], br[nb][3],
                       bAddr + nb * 16 * STRB + ka);
#pragma unroll
            for (int mf = 0; mf < 2; mf++)
#pragma unroll
                for (int nf = 0; nf < 8; nf++) {
                    int nb = nf >> 1, odd = nf & 1;
                    mma16816(acc[mf][nf], a[mf], br[nb][odd], br[nb][odd + 2]);
                }
        }

        // Epilogue: acc already 20*log2e*cos -> single ex2 per element.
        float csA[8], csB[8];
#pragma unroll
        for (int nf = 0; nf < 8; nf++) { csA[nf] = 0.0f; csB[nf] = 0.0f; }
#pragma unroll
        for (int mf = 0; mf < 2; mf++) {
            int gr0 = rowBase + warp_m * 32 + mf * 16 + q;
            int gr1 = gr0 + 8;
#pragma unroll
            for (int nf = 0; nf < 8; nf++) {
                int gc = colBase + warp_n * 64 + nf * 8 + rm * 2;
                float e0 = ex2(acc[mf][nf][0]);
                float e1 = ex2(acc[mf][nf][1]);
                float e2 = ex2(acc[mf][nf][2]);
                float e3 = ex2(acc[mf][nf][3]);
                if (diag) {
                    if (gr0 == gc)     e0 = 0.0f;
                    if (gr0 == gc + 1) e1 = 0.0f;
                    if (gr1 == gc)     e2 = 0.0f;
                    if (gr1 == gc + 1) e3 = 0.0f;
                }
                rs[mf][0] += e0 + e1;
                rs[mf][1] += e2 + e3;
                csA[nf] += e0 + e2;
                csB[nf] += e1 + e3;
            }
        }

        if (!diag) {
            // Reduce col sums over the 8 rows-per-lane-group (q), then REDG.
#pragma unroll
            for (int nf = 0; nf < 8; nf++) {
#pragma unroll
                for (int o = 4; o <= 16; o <<= 1) {
                    csA[nf] += __shfl_xor_sync(0xffffffffu, csA[nf], o);
                    csB[nf] += __shfl_xor_sync(0xffffffffu, csB[nf], o);
                }
            }
            if (q == 0) {
                float* dst = &g_rowsum[colBase + warp_n * 64 + rm * 2];
#pragma unroll
                for (int nf = 0; nf < 8; nf++) {
                    atomicAdd(dst + nf * 8,     csA[nf]);
                    atomicAdd(dst + nf * 8 + 1, csB[nf]);
                }
            }
        }

        // Single barrier per tile: prefetch landed + buffer retire.
        asm volatile("cp.async.wait_group 0;" ::: "memory");
        __syncthreads();
    }

    // Row sums: reduce across rm, then across warp_n via smem, then one REDG.
#pragma unroll
    for (int mf = 0; mf < 2; mf++) {
        float s0 = rs[mf][0], s1 = rs[mf][1];
        s0 += __shfl_xor_sync(0xffffffffu, s0, 1);
        s0 += __shfl_xor_sync(0xffffffffu, s0, 2);
        s1 += __shfl_xor_sync(0xffffffffu, s1, 1);
        s1 += __shfl_xor_sync(0xffffffffu, s1, 2);
        if (rm == 0) {
            int r0 = warp_m * 32 + mf * 16 + q;
            atomicAdd(&rsum[r0], s0);
            atomicAdd(&rsum[r0 + 8], s1);
        }
    }
    __syncthreads();
    if (tid < TILE) atomicAdd(&g_rowsum[rowBase + tid], rsum[tid]);
}

// ---------------------------------------------------------------------------
__global__ void finalize_kernel(float* out) {
    __shared__ float red[32];
    int tid = threadIdx.x;
    float l = 0.0f;
    for (int i = tid; i < NROWS; i += 1024)
        l += AINV * g_tdot[i >> 1] - logf(g_rowsum[i]);
#pragma unroll
    for (int o = 16; o; o >>= 1) l += __shfl_xor_sync(0xffffffffu, l, o);
    if ((tid & 31) == 0) red[tid >> 5] = l;
    __syncthreads();
    if (tid < 32) {
        float v = red[tid];
#pragma unroll
        for (int o = 16; o; o >>= 1) v += __shfl_xor_sync(0xffffffffu, v, o);
        if (tid == 0) out[0] = -v * (1.0f / NROWS);
    }
}

// ---------------------------------------------------------------------------
extern "C" void kernel_launch(void* const* d_in, const int* in_sizes, int n_in,
                              void* d_out, int out_size) {
    const float* in = (const float*)d_in[0];
    float* out = (float*)d_out;
    (void)in_sizes; (void)n_in; (void)out_size;

    int dynBytes = 3 * ABYTES;   // 104448
    (void)cudaFuncSetAttribute(expsum_mma_kernel,
                               cudaFuncAttributeMaxDynamicSharedMemorySize,
                               dynBytes);

    normalize_kernel<<<NROWS / 2 / 8, 256>>>(in);
    expsum_mma_kernel<<<NCTAS, 256, dynBytes>>>();
    finalize_kernel<<<1, 1024>>>(out);
}

// round 14
// speedup vs baseline: 1.2242x; 1.0733x over previous
#include <cuda_runtime.h>
#include <cuda_bf16.h>
#include <math.h>
#include <cstdint>

// CSELoss: loss = -mean_i [ s(i,i^1) - log(sum_{j!=i} exp(s_ij)) ], s = Xn Xn^T / alpha.
// Upper-triangle only; A-resident chunks (CHUNK=8, single wave), cp.async
// double-buffered B, one barrier per tile, col-sums via direct gmem REDG.
// Operands pre-scaled by sqrt(20*log2 e) -> epilogue is a single ex2 per element.

#define NROWS 8192
#define DD    128
#define TILE  128
#define AINV  20.0f
#define SQSC  5.37158769f             // sqrt(20 * log2(e))
#define NT    (NROWS / TILE)          // 64
#define CHUNK 8
#define NCTAS 288                     // sum_{n=1..64} ceil(n/8)
#define STRB  272
#define ABYTES (128 * STRB)           // 34816

__device__ __nv_bfloat16  g_xb[NROWS * DD];
__device__ float          g_rowsum[NROWS];
__device__ float          g_tdot[NROWS / 2];

// ---------------------------------------------------------------------------
__device__ __forceinline__ uint32_t smem_u32(const void* p) {
    uint32_t a;
    asm("{ .reg .u64 t; cvta.to.shared.u64 t, %1; cvt.u32.u64 %0, t; }" : "=r"(a) : "l"(p));
    return a;
}
__device__ __forceinline__ void cp16(uint32_t dst, const void* src) {
    asm volatile("cp.async.cg.shared.global [%0], [%1], 16;" :: "r"(dst), "l"(src));
}
__device__ __forceinline__ void ldm_x4(uint32_t& r0, uint32_t& r1, uint32_t& r2,
                                       uint32_t& r3, uint32_t addr) {
    asm volatile("ldmatrix.sync.aligned.m8n8.x4.shared.b16 {%0,%1,%2,%3}, [%4];"
                 : "=r"(r0), "=r"(r1), "=r"(r2), "=r"(r3) : "r"(addr));
}
__device__ __forceinline__ void mma16816(float* c, const uint32_t* a,
                                         uint32_t b0, uint32_t b1) {
    asm volatile("mma.sync.aligned.m16n8k16.row.col.f32.bf16.bf16.f32 "
                 "{%0,%1,%2,%3}, {%4,%5,%6,%7}, {%8,%9}, {%0,%1,%2,%3};"
                 : "+f"(c[0]), "+f"(c[1]), "+f"(c[2]), "+f"(c[3])
                 : "r"(a[0]), "r"(a[1]), "r"(a[2]), "r"(a[3]), "r"(b0), "r"(b1));
}
__device__ __forceinline__ float ex2(float x) {
    float y;
    asm("ex2.approx.ftz.f32 %0, %1;" : "=f"(y) : "f"(x));
    return y;
}
__device__ __forceinline__ uint32_t pack_bf16x2(float lo, float hi) {
    uint32_t r;
    asm("cvt.rn.bf16x2.f32 %0, %1, %2;" : "=r"(r) : "f"(hi), "f"(lo));
    return r;
}

// ---------------------------------------------------------------------------
// One warp per PAIR of rows; zeros g_rowsum and out[0].
__global__ void normalize_kernel(const float* __restrict__ in, float* out) {
    int gtid = blockIdx.x * blockDim.x + threadIdx.x;
    if (gtid < NROWS) g_rowsum[gtid] = 0.0f;
    if (gtid == 0) out[0] = 0.0f;
    int p    = gtid >> 5;
    int lane = threadIdx.x & 31;
    if (p >= NROWS / 2) return;
    int r0 = p * 2;
    float4 v0 = ((const float4*)(in + (size_t)r0 * DD))[lane];
    float4 v1 = ((const float4*)(in + (size_t)(r0 + 1) * DD))[lane];
    float ss0 = v0.x*v0.x + v0.y*v0.y + v0.z*v0.z + v0.w*v0.w;
    float ss1 = v1.x*v1.x + v1.y*v1.y + v1.z*v1.z + v1.w*v1.w;
    float d   = v0.x*v1.x + v0.y*v1.y + v0.z*v1.z + v0.w*v1.w;
#pragma unroll
    for (int o = 16; o; o >>= 1) {
        ss0 += __shfl_xor_sync(0xffffffffu, ss0, o);
        ss1 += __shfl_xor_sync(0xffffffffu, ss1, o);
        d   += __shfl_xor_sync(0xffffffffu, d,   o);
    }
    float i0 = 1.0f / fmaxf(sqrtf(ss0), 1e-8f);
    float i1 = 1.0f / fmaxf(sqrtf(ss1), 1e-8f);
    if (lane == 0) g_tdot[p] = d * i0 * i1;
    float s0 = i0 * SQSC, s1 = i1 * SQSC;
    uint2 w0, w1;
    w0.x = pack_bf16x2(v0.x * s0, v0.y * s0);
    w0.y = pack_bf16x2(v0.z * s0, v0.w * s0);
    w1.x = pack_bf16x2(v1.x * s1, v1.y * s1);
    w1.y = pack_bf16x2(v1.z * s1, v1.w * s1);
    ((uint2*)(g_xb + (size_t)r0 * DD))[lane]       = w0;
    ((uint2*)(g_xb + (size_t)(r0 + 1) * DD))[lane] = w1;
}

// ---------------------------------------------------------------------------
__global__ __launch_bounds__(256, 2)
void expsum_mma_kernel() {
    extern __shared__ __align__(16) char sm[];
    uint32_t sA  = smem_u32(sm);
    uint32_t sB0 = sA + ABYTES;
    uint32_t sB1 = sB0 + ABYTES;
    __shared__ float rsum[TILE];

    int tid  = threadIdx.x;
    int lane = tid & 31;
    int wid  = tid >> 5;
    int warp_m = wid & 3;
    int warp_n = wid >> 2;

    int t = blockIdx.x, bi = 0;
    int cpb = (NT + CHUNK - 1) / CHUNK;
    while (t >= cpb) { t -= cpb; bi++; cpb = (NT - bi + CHUNK - 1) / CHUNK; }
    int bjStart = bi + t * CHUNK;
    int ntile   = min(CHUNK, NT - bjStart);
    int rowBase = bi * TILE;

    int r8 = tid >> 4;
    int c8 = (tid & 15) << 3;
#pragma unroll
    for (int it = 0; it < 8; it++) {
        int r = r8 + it * 16;
        uint32_t so = (uint32_t)r * STRB + (uint32_t)c8 * 2;
        cp16(sA + so,  &g_xb[(size_t)(rowBase + r) * DD + c8]);
        cp16(sB0 + so, &g_xb[(size_t)(bjStart * TILE + r) * DD + c8]);
    }
    asm volatile("cp.async.commit_group;");
    if (tid < TILE) rsum[tid] = 0.0f;
    asm volatile("cp.async.wait_group 0;" ::: "memory");
    __syncthreads();

    uint32_t lrow = lane & 15;
    uint32_t lcol = (lane >> 4) << 4;
    uint32_t aAddr  = sA + (warp_m * 32 + lrow) * STRB + lcol;
    uint32_t bLocal = (warp_n * 64 + lrow) * STRB + lcol;

    int q = lane >> 2, rm = lane & 3;
    float rs[2][2] = {{0.f, 0.f}, {0.f, 0.f}};

    for (int tt = 0; tt < ntile; tt++) {
        int bj = bjStart + tt;
        bool diag = (bj == bi);
        int colBase = bj * TILE;
        uint32_t bCur = (tt & 1) ? sB1 : sB0;
        uint32_t bNxt = (tt & 1) ? sB0 : sB1;

        if (tt + 1 < ntile) {
#pragma unroll
            for (int it = 0; it < 8; it++) {
                int r = r8 + it * 16;
                cp16(bNxt + (uint32_t)r * STRB + (uint32_t)c8 * 2,
                     &g_xb[(size_t)((bj + 1) * TILE + r) * DD + c8]);
            }
            asm volatile("cp.async.commit_group;");
        }

        float acc[2][8][4];
#pragma unroll
        for (int mf = 0; mf < 2; mf++)
#pragma unroll
            for (int nf = 0; nf < 8; nf++)
#pragma unroll
                for (int e = 0; e < 4; e++) acc[mf][nf][e] = 0.0f;

        uint32_t bAddr = bCur + bLocal;
#pragma unroll
        for (int kk = 0; kk < 8; kk++) {
            uint32_t ka = kk * 32;
            uint32_t a[2][4];
            ldm_x4(a[0][0], a[0][1], a[0][2], a[0][3], aAddr + ka);
            ldm_x4(a[1][0], a[1][1], a[1][2], a[1][3], aAddr + 16 * STRB + ka);
            uint32_t br[4][4];
#pragma unroll
            for (int nb = 0; nb < 4; nb++)
                ldm_x4(br[nb][0], br[nb][1], br[nb][2], br[nb][3],
                       bAddr + nb * 16 * STRB + ka);
#pragma unroll
            for (int mf = 0; mf < 2; mf++)
#pragma unroll
                for (int nf = 0; nf < 8; nf++) {
                    int nb = nf >> 1, odd = nf & 1;
                    mma16816(acc[mf][nf], a[mf], br[nb][odd], br[nb][odd + 2]);
                }
        }

        // Epilogue: acc already 20*log2e*cos -> single ex2 per element.
        float csA[8], csB[8];
#pragma unroll
        for (int nf = 0; nf < 8; nf++) { csA[nf] = 0.0f; csB[nf] = 0.0f; }
#pragma unroll
        for (int mf = 0; mf < 2; mf++) {
            int gr0 = rowBase + warp_m * 32 + mf * 16 + q;
            int gr1 = gr0 + 8;
#pragma unroll
            for (int nf = 0; nf < 8; nf++) {
                int gc = colBase + warp_n * 64 + nf * 8 + rm * 2;
                float e0 = ex2(acc[mf][nf][0]);
                float e1 = ex2(acc[mf][nf][1]);
                float e2 = ex2(acc[mf][nf][2]);
                float e3 = ex2(acc[mf][nf][3]);
                if (diag) {
                    if (gr0 == gc)     e0 = 0.0f;
                    if (gr0 == gc + 1) e1 = 0.0f;
                    if (gr1 == gc)     e2 = 0.0f;
                    if (gr1 == gc + 1) e3 = 0.0f;
                }
                rs[mf][0] += e0 + e1;
                rs[mf][1] += e2 + e3;
                csA[nf] += e0 + e2;
                csB[nf] += e1 + e3;
            }
        }

        if (!diag) {
#pragma unroll
            for (int nf = 0; nf < 8; nf++) {
#pragma unroll
                for (int o = 4; o <= 16; o <<= 1) {
                    csA[nf] += __shfl_xor_sync(0xffffffffu, csA[nf], o);
                    csB[nf] += __shfl_xor_sync(0xffffffffu, csB[nf], o);
                }
            }
            if (q == 0) {
                float* dst = &g_rowsum[colBase + warp_n * 64 + rm * 2];
#pragma unroll
                for (int nf = 0; nf < 8; nf++) {
                    atomicAdd(dst + nf * 8,     csA[nf]);
                    atomicAdd(dst + nf * 8 + 1, csB[nf]);
                }
            }
        }

        asm volatile("cp.async.wait_group 0;" ::: "memory");
        __syncthreads();
    }

#pragma unroll
    for (int mf = 0; mf < 2; mf++) {
        float s0 = rs[mf][0], s1 = rs[mf][1];
        s0 += __shfl_xor_sync(0xffffffffu, s0, 1);
        s0 += __shfl_xor_sync(0xffffffffu, s0, 2);
        s1 += __shfl_xor_sync(0xffffffffu, s1, 1);
        s1 += __shfl_xor_sync(0xffffffffu, s1, 2);
        if (rm == 0) {
            int r0 = warp_m * 32 + mf * 16 + q;
            atomicAdd(&rsum[r0], s0);
            atomicAdd(&rsum[r0 + 8], s1);
        }
    }
    __syncthreads();
    if (tid < TILE) atomicAdd(&g_rowsum[rowBase + tid], rsum[tid]);
}

// ---------------------------------------------------------------------------
// One row per thread (32 CTAs x 256): max memory parallelism, __logf, one
// atomicAdd per warp into pre-zeroed out[0].
__global__ void finalize_kernel(float* out) {
    int i    = blockIdx.x * blockDim.x + threadIdx.x;
    int lane = threadIdx.x & 31;
    float l = AINV * g_tdot[i >> 1] - __logf(g_rowsum[i]);
#pragma unroll
    for (int o = 16; o; o >>= 1) l += __shfl_xor_sync(0xffffffffu, l, o);
    if (lane == 0) atomicAdd(out, -l * (1.0f / NROWS));
}

// ---------------------------------------------------------------------------
extern "C" void kernel_launch(void* const* d_in, const int* in_sizes, int n_in,
                              void* d_out, int out_size) {
    const float* in = (const float*)d_in[0];
    float* out = (float*)d_out;
    (void)in_sizes; (void)n_in; (void)out_size;

    int dynBytes = 3 * ABYTES;   // 104448
    (void)cudaFuncSetAttribute(expsum_mma_kernel,
                               cudaFuncAttributeMaxDynamicSharedMemorySize,
                               dynBytes);

    normalize_kernel<<<NROWS / 2 / 8, 256>>>(in, out);
    expsum_mma_kernel<<<NCTAS, 256, dynBytes>>>();
    finalize_kernel<<<NROWS / 256, 256>>>(out);
}

// round 15
// speedup vs baseline: 1.2450x; 1.0170x over previous
#include <cuda_runtime.h>
#include <cuda_bf16.h>
#include <math.h>
#include <cstdint>

// CSELoss: loss = -mean_i [ s(i,i^1) - log(sum_{j!=i} exp(s_ij)) ], s = Xn Xn^T / alpha.
// Upper-triangle only; A-resident chunks (CHUNK=8, single wave), B tiles cycled
// through a 2-slot mbarrier ring (no per-tile __syncthreads -> warps drift and
// overlap MUFU epilogue with HMMA mainloop). Operands pre-scaled by
// sqrt(20*log2 e) -> epilogue is a single ex2 per element.

#define NROWS 8192
#define DD    128
#define TILE  128
#define AINV  20.0f
#define SQSC  5.37158769f             // sqrt(20 * log2(e))
#define NT    (NROWS / TILE)          // 64
#define CHUNK 8
#define NCTAS 288                     // sum_{n=1..64} ceil(n/8)
#define STRB  272
#define ABYTES (128 * STRB)           // 34816

__device__ __nv_bfloat16  g_xb[NROWS * DD];
__device__ float          g_rowsum[NROWS];
__device__ float          g_tdot[NROWS / 2];

// ---------------------------------------------------------------------------
__device__ __forceinline__ uint32_t smem_u32(const void* p) {
    uint32_t a;
    asm("{ .reg .u64 t; cvta.to.shared.u64 t, %1; cvt.u32.u64 %0, t; }" : "=r"(a) : "l"(p));
    return a;
}
__device__ __forceinline__ void cp16(uint32_t dst, const void* src) {
    asm volatile("cp.async.cg.shared.global [%0], [%1], 16;" :: "r"(dst), "l"(src));
}
__device__ __forceinline__ void ldm_x4(uint32_t& r0, uint32_t& r1, uint32_t& r2,
                                       uint32_t& r3, uint32_t addr) {
    asm volatile("ldmatrix.sync.aligned.m8n8.x4.shared.b16 {%0,%1,%2,%3}, [%4];"
                 : "=r"(r0), "=r"(r1), "=r"(r2), "=r"(r3) : "r"(addr));
}
__device__ __forceinline__ void mma16816(float* c, const uint32_t* a,
                                         uint32_t b0, uint32_t b1) {
    asm volatile("mma.sync.aligned.m16n8k16.row.col.f32.bf16.bf16.f32 "
                 "{%0,%1,%2,%3}, {%4,%5,%6,%7}, {%8,%9}, {%0,%1,%2,%3};"
                 : "+f"(c[0]), "+f"(c[1]), "+f"(c[2]), "+f"(c[3])
                 : "r"(a[0]), "r"(a[1]), "r"(a[2]), "r"(a[3]), "r"(b0), "r"(b1));
}
__device__ __forceinline__ float ex2(float x) {
    float y;
    asm("ex2.approx.ftz.f32 %0, %1;" : "=f"(y) : "f"(x));
    return y;
}
__device__ __forceinline__ uint32_t pack_bf16x2(float lo, float hi) {
    uint32_t r;
    asm("cvt.rn.bf16x2.f32 %0, %1, %2;" : "=r"(r) : "f"(hi), "f"(lo));
    return r;
}
__device__ __forceinline__ void mbar_init(uint32_t mb, uint32_t cnt) {
    asm volatile("mbarrier.init.shared.b64 [%0], %1;" :: "r"(mb), "r"(cnt) : "memory");
}
__device__ __forceinline__ void mbar_arrive(uint32_t mb) {
    asm volatile("mbarrier.arrive.shared.b64 _, [%0];" :: "r"(mb) : "memory");
}
__device__ __forceinline__ void cp_arrive_noinc(uint32_t mb) {
    asm volatile("cp.async.mbarrier.arrive.noinc.shared.b64 [%0];" :: "r"(mb) : "memory");
}
__device__ __forceinline__ void mbar_wait(uint32_t mb, uint32_t parity) {
    asm volatile(
        "{\n\t.reg .pred P;\n\t"
        "W_%=:\n\t"
        "mbarrier.try_wait.parity.acquire.cta.shared::cta.b64 P, [%0], %1, 0x989680;\n\t"
        "@P bra.uni D_%=;\n\t"
        "bra.uni W_%=;\n\t"
        "D_%=:\n\t}"
        :: "r"(mb), "r"(parity) : "memory");
}

// ---------------------------------------------------------------------------
// 2 warps per pair (1024 CTAs): each warp handles a 64-col half of both rows;
// halves exchange partial reductions via smem. Also zeros g_rowsum and out.
__global__ void normalize_kernel(const float* __restrict__ in, float* out) {
    int gtid = blockIdx.x * blockDim.x + threadIdx.x;
    if (gtid < NROWS) g_rowsum[gtid] = 0.0f;
    if (gtid == 0) out[0] = 0.0f;
    int lane = threadIdx.x & 31;
    int wl   = threadIdx.x >> 5;      // local warp 0..7
    int w    = gtid >> 5;             // global warp
    int p    = w >> 1;                // pair index 0..4095
    int h    = w & 1;                 // column half
    int r0   = p * 2;
    int col  = h * 64 + lane * 2;

    float2 a0 = *(const float2*)(in + (size_t)r0 * DD + col);
    float2 a1 = *(const float2*)(in + (size_t)(r0 + 1) * DD + col);
    float ss0 = a0.x * a0.x + a0.y * a0.y;
    float ss1 = a1.x * a1.x + a1.y * a1.y;
    float d   = a0.x * a1.x + a0.y * a1.y;
#pragma unroll
    for (int o = 16; o; o >>= 1) {
        ss0 += __shfl_xor_sync(0xffffffffu, ss0, o);
        ss1 += __shfl_xor_sync(0xffffffffu, ss1, o);
        d   += __shfl_xor_sync(0xffffffffu, d,   o);
    }
    __shared__ float sred[8][3];
    if (lane == 0) { sred[wl][0] = ss0; sred[wl][1] = ss1; sred[wl][2] = d; }
    __syncthreads();
    int pw = wl ^ 1;
    float t0 = sred[wl][0] + sred[pw][0];
    float t1 = sred[wl][1] + sred[pw][1];
    float td = sred[wl][2] + sred[pw][2];
    float i0 = 1.0f / fmaxf(sqrtf(t0), 1e-8f);
    float i1 = 1.0f / fmaxf(sqrtf(t1), 1e-8f);
    if (h == 0 && lane == 0) g_tdot[p] = td * i0 * i1;
    float s0 = i0 * SQSC, s1 = i1 * SQSC;
    ((uint32_t*)(g_xb + (size_t)r0 * DD))[h * 32 + lane] =
        pack_bf16x2(a0.x * s0, a0.y * s0);
    ((uint32_t*)(g_xb + (size_t)(r0 + 1) * DD))[h * 32 + lane] =
        pack_bf16x2(a1.x * s1, a1.y * s1);
}

// ---------------------------------------------------------------------------
__global__ __launch_bounds__(256, 2)
void expsum_mma_kernel() {
    extern __shared__ __align__(16) char sm[];
    uint32_t sA  = smem_u32(sm);
    uint32_t sB0 = sA + ABYTES;
    uint32_t sB1 = sB0 + ABYTES;
    __shared__ float rsum[TILE];
    __shared__ __align__(8) unsigned long long mbar[4];  // f0 f1 e0 e1
    uint32_t mb = smem_u32(mbar);

    int tid  = threadIdx.x;
    int lane = tid & 31;
    int wid  = tid >> 5;
    int warp_m = wid & 3;
    int warp_n = wid >> 2;

    int t = blockIdx.x, bi = 0;
    int cpb = (NT + CHUNK - 1) / CHUNK;
    while (t >= cpb) { t -= cpb; bi++; cpb = (NT - bi + CHUNK - 1) / CHUNK; }
    int bjStart = bi + t * CHUNK;
    int ntile   = min(CHUNK, NT - bjStart);
    int rowBase = bi * TILE;

    if (tid == 0) {
        mbar_init(mb,      256);   // full[0]: one cp-completion arrive per thread
        mbar_init(mb + 8,  256);   // full[1]
        mbar_init(mb + 16, 8);     // empty[0]: one arrive per warp
        mbar_init(mb + 24, 8);     // empty[1]
    }
    if (tid < TILE) rsum[tid] = 0.0f;
    __syncthreads();

    // Startup: A + B0, completion arms full[0].
    int r8 = tid >> 4;
    int c8 = (tid & 15) << 3;
#pragma unroll
    for (int it = 0; it < 8; it++) {
        int r = r8 + it * 16;
        uint32_t so = (uint32_t)r * STRB + (uint32_t)c8 * 2;
        cp16(sA + so,  &g_xb[(size_t)(rowBase + r) * DD + c8]);
        cp16(sB0 + so, &g_xb[(size_t)(bjStart * TILE + r) * DD + c8]);
    }
    cp_arrive_noinc(mb);   // full[0]

    uint32_t lrow = lane & 15;
    uint32_t lcol = (lane >> 4) << 4;
    uint32_t aAddr  = sA + (warp_m * 32 + lrow) * STRB + lcol;
    uint32_t bLocal = (warp_n * 64 + lrow) * STRB + lcol;

    int q = lane >> 2, rm = lane & 3;
    float rs[2][2] = {{0.f, 0.f}, {0.f, 0.f}};

    for (int tt = 0; tt < ntile; tt++) {
        int bj = bjStart + tt;
        bool diag = (bj == bi);
        int colBase = bj * TILE;
        int buf = tt & 1, nb = buf ^ 1;
        uint32_t bCur = buf ? sB1 : sB0;
        uint32_t bNxt = buf ? sB0 : sB1;

        // Consume current B tile.
        mbar_wait(mb + buf * 8, (uint32_t)((tt >> 1) & 1));

        float acc[2][8][4];
#pragma unroll
        for (int mf = 0; mf < 2; mf++)
#pragma unroll
            for (int nf = 0; nf < 8; nf++)
#pragma unroll
                for (int e = 0; e < 4; e++) acc[mf][nf][e] = 0.0f;

        uint32_t bAddr = bCur + bLocal;
#pragma unroll
        for (int kk = 0; kk < 8; kk++) {
            uint32_t ka = kk * 32;
            uint32_t a[2][4];
            ldm_x4(a[0][0], a[0][1], a[0][2], a[0][3], aAddr + ka);
            ldm_x4(a[1][0], a[1][1], a[1][2], a[1][3], aAddr + 16 * STRB + ka);
            uint32_t br[4][4];
#pragma unroll
            for (int nb2 = 0; nb2 < 4; nb2++)
                ldm_x4(br[nb2][0], br[nb2][1], br[nb2][2], br[nb2][3],
                       bAddr + nb2 * 16 * STRB + ka);
#pragma unroll
            for (int mf = 0; mf < 2; mf++)
#pragma unroll
                for (int nf = 0; nf < 8; nf++) {
                    int nb3 = nf >> 1, odd = nf & 1;
                    mma16816(acc[mf][nf], a[mf], br[nb3][odd], br[nb3][odd + 2]);
                }
        }
        // This warp is done reading bCur.
        if (lane == 0) mbar_arrive(mb + 16 + buf * 8);

        // Prefetch next B tile into bNxt once it's fully retired.
        if (tt + 1 < ntile) {
            mbar_wait(mb + 16 + nb * 8,
                      (uint32_t)((((tt + 1) >> 1) & 1) ^ 1));
#pragma unroll
            for (int it = 0; it < 8; it++) {
                int r = r8 + it * 16;
                cp16(bNxt + (uint32_t)r * STRB + (uint32_t)c8 * 2,
                     &g_xb[(size_t)((bj + 1) * TILE + r) * DD + c8]);
            }
            cp_arrive_noinc(mb + nb * 8);
        }

        // Epilogue: acc already 20*log2e*cos -> single ex2 per element.
        float csA[8], csB[8];
#pragma unroll
        for (int nf = 0; nf < 8; nf++) { csA[nf] = 0.0f; csB[nf] = 0.0f; }
#pragma unroll
        for (int mf = 0; mf < 2; mf++) {
            int gr0 = rowBase + warp_m * 32 + mf * 16 + q;
            int gr1 = gr0 + 8;
#pragma unroll
            for (int nf = 0; nf < 8; nf++) {
                int gc = colBase + warp_n * 64 + nf * 8 + rm * 2;
                float e0 = ex2(acc[mf][nf][0]);
                float e1 = ex2(acc[mf][nf][1]);
                float e2 = ex2(acc[mf][nf][2]);
                float e3 = ex2(acc[mf][nf][3]);
                if (diag) {
                    if (gr0 == gc)     e0 = 0.0f;
                    if (gr0 == gc + 1) e1 = 0.0f;
                    if (gr1 == gc)     e2 = 0.0f;
                    if (gr1 == gc + 1) e3 = 0.0f;
                }
                rs[mf][0] += e0 + e1;
                rs[mf][1] += e2 + e3;
                csA[nf] += e0 + e2;
                csB[nf] += e1 + e3;
            }
        }

        if (!diag) {
#pragma unroll
            for (int nf = 0; nf < 8; nf++) {
#pragma unroll
                for (int o = 4; o <= 16; o <<= 1) {
                    csA[nf] += __shfl_xor_sync(0xffffffffu, csA[nf], o);
                    csB[nf] += __shfl_xor_sync(0xffffffffu, csB[nf], o);
                }
            }
            if (q == 0) {
                float* dst = &g_rowsum[colBase + warp_n * 64 + rm * 2];
#pragma unroll
                for (int nf = 0; nf < 8; nf++) {
                    atomicAdd(dst + nf * 8,     csA[nf]);
                    atomicAdd(dst + nf * 8 + 1, csB[nf]);
                }
            }
        }
    }

    // Row sums: warp-local reduce, smem combine, one gmem add per row.
#pragma unroll
    for (int mf = 0; mf < 2; mf++) {
        float s0 = rs[mf][0], s1 = rs[mf][1];
        s0 += __shfl_xor_sync(0xffffffffu, s0, 1);
        s0 += __shfl_xor_sync(0xffffffffu, s0, 2);
        s1 += __shfl_xor_sync(0xffffffffu, s1, 1);
        s1 += __shfl_xor_sync(0xffffffffu, s1, 2);
        if (rm == 0) {
            int r0 = warp_m * 32 + mf * 16 + q;
            atomicAdd(&rsum[r0], s0);
            atomicAdd(&rsum[r0 + 8], s1);
        }
    }
    __syncthreads();
    if (tid < TILE) atomicAdd(&g_rowsum[rowBase + tid], rsum[tid]);
}

// ---------------------------------------------------------------------------
__global__ void finalize_kernel(float* out) {
    int i    = blockIdx.x * blockDim.x + threadIdx.x;
    int lane = threadIdx.x & 31;
    float l = AINV * g_tdot[i >> 1] - __logf(g_rowsum[i]);
#pragma unroll
    for (int o = 16; o; o >>= 1) l += __shfl_xor_sync(0xffffffffu, l, o);
    if (lane == 0) atomicAdd(out, -l * (1.0f / NROWS));
}

// ---------------------------------------------------------------------------
extern "C" void kernel_launch(void* const* d_in, const int* in_sizes, int n_in,
                              void* d_out, int out_size) {
    const float* in = (const float*)d_in[0];
    float* out = (float*)d_out;
    (void)in_sizes; (void)n_in; (void)out_size;

    int dynBytes = 3 * ABYTES;   // 104448
    (void)cudaFuncSetAttribute(expsum_mma_kernel,
                               cudaFuncAttributeMaxDynamicSharedMemorySize,
                               dynBytes);

    normalize_kernel<<<NROWS / 2 * 2 * 32 / 256, 256>>>(in, out);  // 1024 CTAs
    expsum_mma_kernel<<<NCTAS, 256, dynBytes>>>();
    finalize_kernel<<<NROWS / 256, 256>>>(out);
}